// round 1
// baseline (speedup 1.0000x reference)
#include <cuda_runtime.h>
#include <math.h>

#define NBATCH 256
#define LEN    200
#define DM     256
#define NH     4
#define DK     64
#define NIS    288
#define NTI    10   // item weight types
#define NTQ    9    // intent weight types
#define TILE   16

// ---------------- scratch (static device globals; no allocation) ------------
__device__ float g_Kbs[(size_t)NBATCH * NH * LEN * DK];
__device__ float g_Vbs[(size_t)NBATCH * NH * LEN * DK];
__device__ float g_Kba[(size_t)NBATCH * NH * LEN * DK];
__device__ float g_Vba[(size_t)NBATCH * NH * LEN * DK];
__device__ float g_Q  [(size_t)NBATCH * NH * NIS * DK];

__device__ __forceinline__ float get_cn(float xf) {
    const float quarter = 24.0f / 4.0f;            // 6
    float safe = fmaxf(xf, quarter);
    float f1 = quarter + floorf(logf(4.0f * safe / 24.0f) /
                                logf(4.0f * 200.0f / 24.0f) * quarter);
    float upper = 24.0f / 2.0f - 1.0f;             // 11
    return (xf < quarter) ? xf : fminf(f1, upper);
}

// ---------------------------------------------------------------------------
// Kernel A: item projections.
//   blockIdx.x = t in [0,23):  t<10  -> "Bs" projections for type t (tokens
//                                        with b_seq==t, compacted in smem)
//                              t>=10 -> "Ba" projections (W type 9, all
//                                        tokens), tile (t-10) of 16 tokens
//   blockIdx.y = batch b. 256 threads = 256 output cols, 2 matrices (K & V).
// ---------------------------------------------------------------------------
__global__ __launch_bounds__(256, 2)
void proj_item_kernel(const float* __restrict__ item,
                      const int*   __restrict__ b_seq,
                      const float* __restrict__ W)
{
    int b   = blockIdx.y;
    int t   = blockIdx.x;
    int tid = threadIdx.x;

    __shared__ float xs[TILE][DM];
    __shared__ int   lst[LEN];
    __shared__ int   s_cnt;

    bool isBa = (t >= NTI);
    int  wtype = isBa ? (NTI - 1) : t;
    const float* W0 = W + (size_t)(0 * NTI + wtype) * DM * DM;  // [d][o]
    const float* W1 = W + (size_t)(1 * NTI + wtype) * DM * DM;
    float* K = isBa ? g_Kba : g_Kbs;
    float* V = isBa ? g_Vba : g_Vbs;

    int ntok, base0 = 0, ntiles;
    if (!isBa) {
        if (tid == 0) s_cnt = 0;
        __syncthreads();
        for (int n = tid; n < LEN; n += 256)
            if (b_seq[b * LEN + n] == t) { int p = atomicAdd(&s_cnt, 1); lst[p] = n; }
        __syncthreads();
        ntok   = s_cnt;
        ntiles = (ntok + TILE - 1) / TILE;
    } else {
        base0  = (t - NTI) * TILE;
        ntok   = min(TILE, LEN - base0);
        ntiles = 1;
    }

    int h = tid >> 6, k = tid & 63;
    const float* w0p = W0 + tid;
    const float* w1p = W1 + tid;

    for (int tile = 0; tile < ntiles; ++tile) {
        int tok[TILE];
#pragma unroll
        for (int j = 0; j < TILE; ++j) {
            if (isBa) tok[j] = (j < ntok) ? (base0 + j) : -1;
            else {
                int jj = tile * TILE + j;
                tok[j] = (jj < ntok) ? lst[jj] : -1;
            }
        }
#pragma unroll
        for (int j = 0; j < TILE; ++j) {
            float v = 0.0f;
            if (tok[j] >= 0) v = item[((size_t)(b * LEN + tok[j])) * DM + tid];
            xs[j][tid] = v;
        }
        __syncthreads();

        float acc0[TILE], acc1[TILE];
#pragma unroll
        for (int j = 0; j < TILE; ++j) { acc0[j] = 0.0f; acc1[j] = 0.0f; }

        for (int d4 = 0; d4 < DM / 4; ++d4) {
            int d = d4 * 4;
            float a0 = w0p[(d + 0) * DM], a1 = w0p[(d + 1) * DM];
            float a2 = w0p[(d + 2) * DM], a3 = w0p[(d + 3) * DM];
            float c0 = w1p[(d + 0) * DM], c1 = w1p[(d + 1) * DM];
            float c2 = w1p[(d + 2) * DM], c3 = w1p[(d + 3) * DM];
#pragma unroll
            for (int j = 0; j < TILE; ++j) {
                float4 xv = *reinterpret_cast<const float4*>(&xs[j][d]);
                acc0[j] = fmaf(xv.w, a3, fmaf(xv.z, a2, fmaf(xv.y, a1, fmaf(xv.x, a0, acc0[j]))));
                acc1[j] = fmaf(xv.w, c3, fmaf(xv.z, c2, fmaf(xv.y, c1, fmaf(xv.x, c0, acc1[j]))));
            }
        }
        __syncthreads();
#pragma unroll
        for (int j = 0; j < TILE; ++j) {
            if (tok[j] >= 0) {
                size_t o = (((size_t)b * NH + h) * LEN + tok[j]) * DK + k;
                K[o] = acc0[j];
                V[o] = acc1[j];
            }
        }
    }
}

// ---------------------------------------------------------------------------
// Kernel B: intent projections (Q). blockIdx.x = type t in [0,9),
// blockIdx.y = b. Rows of "intent" with b_seq2[b,q]==t, compacted.
// ---------------------------------------------------------------------------
__global__ __launch_bounds__(256, 2)
void proj_intent_kernel(const float* __restrict__ intent,
                        const int*   __restrict__ b_seq2,
                        const float* __restrict__ W)
{
    int b = blockIdx.y, t = blockIdx.x, tid = threadIdx.x;
    __shared__ float xs[TILE][DM];
    __shared__ int   lst[NIS];
    __shared__ int   s_cnt;

    if (tid == 0) s_cnt = 0;
    __syncthreads();
    for (int n = tid; n < NIS; n += 256)
        if (b_seq2[b * NIS + n] == t) { int p = atomicAdd(&s_cnt, 1); lst[p] = n; }
    __syncthreads();
    int ntok   = s_cnt;
    int ntiles = (ntok + TILE - 1) / TILE;

    const float* wp = W + (size_t)t * DM * DM + tid;   // W_intent[0][t][d][o]
    int h = tid >> 6, k = tid & 63;

    for (int tile = 0; tile < ntiles; ++tile) {
        int tok[TILE];
#pragma unroll
        for (int j = 0; j < TILE; ++j) {
            int jj = tile * TILE + j;
            tok[j] = (jj < ntok) ? lst[jj] : -1;
        }
#pragma unroll
        for (int j = 0; j < TILE; ++j) {
            float v = 0.0f;
            if (tok[j] >= 0) v = intent[(size_t)tok[j] * DM + tid];
            xs[j][tid] = v;
        }
        __syncthreads();

        float acc[TILE];
#pragma unroll
        for (int j = 0; j < TILE; ++j) acc[j] = 0.0f;

        for (int d4 = 0; d4 < DM / 4; ++d4) {
            int d = d4 * 4;
            float a0 = wp[(d + 0) * DM], a1 = wp[(d + 1) * DM];
            float a2 = wp[(d + 2) * DM], a3 = wp[(d + 3) * DM];
#pragma unroll
            for (int j = 0; j < TILE; ++j) {
                float4 xv = *reinterpret_cast<const float4*>(&xs[j][d]);
                acc[j] = fmaf(xv.w, a3, fmaf(xv.z, a2, fmaf(xv.y, a1, fmaf(xv.x, a0, acc[j]))));
            }
        }
        __syncthreads();
#pragma unroll
        for (int j = 0; j < TILE; ++j) {
            if (tok[j] >= 0)
                g_Q[(((size_t)b * NH + h) * NIS + tok[j]) * DK + k] = acc[j];
        }
    }
}

// ---------------------------------------------------------------------------
// Kernel C: attention + softmax + top-k + sparse p@V.
// One block per (b,h). Phase 0: Bs (q-tiles 0..7, K/V = g_Kbs/g_Vbs),
// phase 1: Ba (q-tile 8, K/V = g_Kba/g_Vba).
// Thread layout per 32-query tile: q8 = tid>>3 (query), g = tid&7 (8 lanes,
// each owning 25 contiguous keys).
// ---------------------------------------------------------------------------
__global__ __launch_bounds__(256, 2)
void attn_kernel(const int* __restrict__ mask,
                 const int* __restrict__ type_cnt,
                 float* __restrict__ out)
{
    extern __shared__ char sm[];
    float* Kt    = (float*)sm;              // [64][200]  (transposed K)
    float* Vs    = Kt + 64 * LEN;           // [200][64]
    float* Qs    = Vs + LEN * DK;           // [32][65]   (padded)
    float* keptP = Qs + 32 * 65;            // [32][12]
    int*   keptI = (int*)(keptP + 32 * 12); // [32][12]

    int bh = blockIdx.x;
    int b = bh >> 2, h = bh & 3;
    int tid = threadIdx.x;
    int q8 = tid >> 3, g = tid & 7;
    int nb = g * 25;

    for (int phase = 0; phase < 2; ++phase) {
        const float* Ksrc = (phase == 0 ? g_Kbs : g_Kba) + ((size_t)(b * NH + h)) * LEN * DK;
        const float* Vsrc = (phase == 0 ? g_Vbs : g_Vba) + ((size_t)(b * NH + h)) * LEN * DK;
        for (int idx = tid; idx < LEN * DK; idx += 256) {
            int n = idx >> 6, k = idx & 63;
            Kt[k * LEN + n] = Ksrc[idx];
            Vs[idx]         = Vsrc[idx];
        }
        __syncthreads();

        int t0 = (phase == 0) ? 0 : 8;
        int t1 = (phase == 0) ? 8 : 9;
        for (int jt = t0; jt < t1; ++jt) {
            int qbase = jt * 32;
            float kval;
            if (phase == 0) {
                kval = get_cn((float)type_cnt[b * 9 + 1 + jt]);
            } else {
                int s = 0;
#pragma unroll
                for (int i = 0; i < 9; ++i) s += type_cnt[b * 9 + i];
                kval = get_cn((float)s);
            }
            int kk = (int)ceilf(kval);      // kval is integer-valued, <= 11

            for (int idx = tid; idx < 32 * DK; idx += 256) {
                int q = idx >> 6, k = idx & 63;
                Qs[q * 65 + k] = g_Q[(((size_t)b * NH + h) * NIS + qbase + q) * DK + k];
            }
            __syncthreads();

            // ---- scores: p[i] = Q[q8,:] . K[nb+i,:] ----
            float p[25];
#pragma unroll
            for (int i = 0; i < 25; ++i) p[i] = 0.0f;
            for (int k = 0; k < DK; ++k) {
                float qv = Qs[q8 * 65 + k];
                const float* kr = &Kt[k * LEN + nb];
#pragma unroll
                for (int i = 0; i < 25; ++i) p[i] = fmaf(qv, kr[i], p[i]);
            }

            // ---- scale + mask ----
            const int* mrow = mask + ((size_t)b * NIS + (qbase + q8)) * LEN + nb;
#pragma unroll
            for (int i = 0; i < 25; ++i) {
                float s = p[i] * 0.125f;               // / sqrt(64)
                if (mrow[i] == 0) s = -1e30f;
                p[i] = s;
            }

            // ---- softmax over 200 (8-lane subgroup) ----
            float mx = -3.4e38f;
#pragma unroll
            for (int i = 0; i < 25; ++i) mx = fmaxf(mx, p[i]);
            for (int off = 1; off < 8; off <<= 1)
                mx = fmaxf(mx, __shfl_xor_sync(0xffffffffu, mx, off));
            float sum = 0.0f;
#pragma unroll
            for (int i = 0; i < 25; ++i) { float e = expf(p[i] - mx); p[i] = e; sum += e; }
            for (int off = 1; off < 8; off <<= 1)
                sum += __shfl_xor_sync(0xffffffffu, sum, off);
#pragma unroll
            for (int i = 0; i < 25; ++i) p[i] = p[i] / sum;

            // ---- top-k: kk iterations of argmax with (val desc, idx asc) ----
            for (int it = 0; it < kk; ++it) {
                float bv = -2.0f; int bi = 0x40000000;
#pragma unroll
                for (int i = 0; i < 25; ++i) {
                    if (p[i] > bv) { bv = p[i]; bi = nb + i; }  // strict > keeps earliest idx
                }
                for (int off = 1; off < 8; off <<= 1) {
                    float ov = __shfl_xor_sync(0xffffffffu, bv, off);
                    int   oi = __shfl_xor_sync(0xffffffffu, bi, off);
                    if (ov > bv || (ov == bv && oi < bi)) { bv = ov; bi = oi; }
                }
                if (bi >= nb && bi < nb + 25) p[bi - nb] = -1.0f;  // remove
                if (g == 0) { keptP[q8 * 12 + it] = bv; keptI[q8 * 12 + it] = bi; }
            }
            __syncthreads();

            // ---- sparse output: out[q, d] = sum_j keptP * V[keptI][d] ----
            float4 o0 = {0, 0, 0, 0}, o1 = {0, 0, 0, 0};
            int d0 = g * 8;
            for (int j = 0; j < kk; ++j) {
                float pv = keptP[q8 * 12 + j];
                int   n  = keptI[q8 * 12 + j];
                const float4* vr = reinterpret_cast<const float4*>(&Vs[n * DK + d0]);
                float4 v0 = vr[0], v1 = vr[1];
                o0.x = fmaf(pv, v0.x, o0.x); o0.y = fmaf(pv, v0.y, o0.y);
                o0.z = fmaf(pv, v0.z, o0.z); o0.w = fmaf(pv, v0.w, o0.w);
                o1.x = fmaf(pv, v1.x, o1.x); o1.y = fmaf(pv, v1.y, o1.y);
                o1.z = fmaf(pv, v1.z, o1.z); o1.w = fmaf(pv, v1.w, o1.w);
            }
            float* orow = out + ((size_t)b * NIS + (qbase + q8)) * (NH * DK) + h * DK + d0;
            reinterpret_cast<float4*>(orow)[0] = o0;
            reinterpret_cast<float4*>(orow)[1] = o1;
            __syncthreads();
        }
        __syncthreads();
    }
}

// ---------------------------------------------------------------------------
static const int ATTN_SMEM = (64 * LEN + LEN * DK + 32 * 65 + 32 * 12) * 4 + 32 * 12 * 4;

extern "C" void kernel_launch(void* const* d_in, const int* in_sizes, int n_in,
                              void* d_out, int out_size)
{
    const float* item     = (const float*)d_in[0];
    const float* intent   = (const float*)d_in[1];
    const int*   mask     = (const int*)  d_in[2];
    const int*   b_seq    = (const int*)  d_in[3];
    const int*   b_seq2   = (const int*)  d_in[4];
    const int*   type_cnt = (const int*)  d_in[5];
    const float* W_item   = (const float*)d_in[6];
    const float* W_intent = (const float*)d_in[7];
    float* out = (float*)d_out;

    cudaFuncSetAttribute(attn_kernel, cudaFuncAttributeMaxDynamicSharedMemorySize, ATTN_SMEM);

    proj_item_kernel  <<<dim3(NTI + (LEN + TILE - 1) / TILE, NBATCH), 256>>>(item, b_seq, W_item);
    proj_intent_kernel<<<dim3(NTQ, NBATCH), 256>>>(intent, b_seq2, W_intent);
    attn_kernel       <<<NBATCH * NH, 256, ATTN_SMEM>>>(mask, type_cnt, out);
}

// round 2
// speedup vs baseline: 1.1968x; 1.1968x over previous
#include <cuda_runtime.h>
#include <math.h>

#define NBATCH 256
#define LEN    200
#define DM     256
#define NH     4
#define DK     64
#define NIS    288
#define NTI    10   // item weight types
#define NTQ    9    // intent weight types
#define TILE   16

// ---------------- scratch (static device globals; no allocation) ------------
__device__ float g_Kbs[(size_t)NBATCH * NH * LEN * DK];
__device__ float g_Vbs[(size_t)NBATCH * NH * LEN * DK];
__device__ float g_Kba[(size_t)NBATCH * NH * LEN * DK];
__device__ float g_Vba[(size_t)NBATCH * NH * LEN * DK];
__device__ float g_Q  [(size_t)NBATCH * NH * NIS * DK];

__device__ __forceinline__ float get_cn(float xf) {
    const float quarter = 24.0f / 4.0f;            // 6
    float safe = fmaxf(xf, quarter);
    float f1 = quarter + floorf(logf(4.0f * safe / 24.0f) /
                                logf(4.0f * 200.0f / 24.0f) * quarter);
    float upper = 24.0f / 2.0f - 1.0f;             // 11
    return (xf < quarter) ? xf : fminf(f1, upper);
}

// ---------------------------------------------------------------------------
// Kernel A: item projections (K & V), software-pipelined weight loads.
//   blockIdx.x = t in [0,23):  t<10 -> per-type "Bs" tokens (compacted)
//                              t>=10 -> "Ba" (all tokens, W type 9), tile t-10
//   blockIdx.y = batch b. 256 threads = 256 output cols, 2 matrices.
// ---------------------------------------------------------------------------
__global__ __launch_bounds__(256, 3)
void proj_item_kernel(const float* __restrict__ item,
                      const int*   __restrict__ b_seq,
                      const float* __restrict__ W)
{
    int b   = blockIdx.y;
    int t   = blockIdx.x;
    int tid = threadIdx.x;

    __shared__ float xs[TILE][DM];
    __shared__ int   lst[LEN];
    __shared__ int   s_cnt;

    bool isBa = (t >= NTI);
    int  wtype = isBa ? (NTI - 1) : t;
    const float* W0 = W + (size_t)(0 * NTI + wtype) * DM * DM;  // [d][o]
    const float* W1 = W + (size_t)(1 * NTI + wtype) * DM * DM;
    float* K = isBa ? g_Kba : g_Kbs;
    float* V = isBa ? g_Vba : g_Vbs;

    int ntok;
    if (!isBa) {
        if (tid == 0) s_cnt = 0;
        __syncthreads();
        for (int n = tid; n < LEN; n += 256)
            if (b_seq[b * LEN + n] == t) { int p = atomicAdd(&s_cnt, 1); lst[p] = n; }
        __syncthreads();
        ntok = s_cnt;
    } else {
        int base0 = (t - NTI) * TILE;
        ntok = min(TILE, LEN - base0);
        for (int i = tid; i < ntok; i += 256) lst[i] = base0 + i;
        __syncthreads();
    }
    int ntiles = (ntok + TILE - 1) / TILE;

    int h = tid >> 6, k = tid & 63;
    const float* w0p = W0 + tid;
    const float* w1p = W1 + tid;

    for (int tile = 0; tile < ntiles; ++tile) {
        int tb = tile * TILE;
#pragma unroll
        for (int j = 0; j < TILE; ++j) {
            int jj = tb + j;
            float v = 0.0f;
            if (jj < ntok) v = item[((size_t)(b * LEN + lst[jj])) * DM + tid];
            xs[j][tid] = v;
        }
        __syncthreads();

        float acc0[TILE], acc1[TILE];
#pragma unroll
        for (int j = 0; j < TILE; ++j) { acc0[j] = 0.0f; acc1[j] = 0.0f; }

        // software-pipelined weight prefetch (math order unchanged)
        float a0 = w0p[0 * DM], a1 = w0p[1 * DM], a2 = w0p[2 * DM], a3 = w0p[3 * DM];
        float c0 = w1p[0 * DM], c1 = w1p[1 * DM], c2 = w1p[2 * DM], c3 = w1p[3 * DM];

        for (int d4 = 0; d4 < DM / 4; ++d4) {
            int dn = (d4 + 1 < DM / 4) ? (d4 + 1) * 4 : 0;
            float na0 = w0p[(dn + 0) * DM], na1 = w0p[(dn + 1) * DM];
            float na2 = w0p[(dn + 2) * DM], na3 = w0p[(dn + 3) * DM];
            float nc0 = w1p[(dn + 0) * DM], nc1 = w1p[(dn + 1) * DM];
            float nc2 = w1p[(dn + 2) * DM], nc3 = w1p[(dn + 3) * DM];
            int d = d4 * 4;
#pragma unroll
            for (int j = 0; j < TILE; ++j) {
                float4 xv = *reinterpret_cast<const float4*>(&xs[j][d]);
                acc0[j] = fmaf(xv.w, a3, fmaf(xv.z, a2, fmaf(xv.y, a1, fmaf(xv.x, a0, acc0[j]))));
                acc1[j] = fmaf(xv.w, c3, fmaf(xv.z, c2, fmaf(xv.y, c1, fmaf(xv.x, c0, acc1[j]))));
            }
            a0 = na0; a1 = na1; a2 = na2; a3 = na3;
            c0 = nc0; c1 = nc1; c2 = nc2; c3 = nc3;
        }
#pragma unroll
        for (int j = 0; j < TILE; ++j) {
            int jj = tb + j;
            if (jj < ntok) {
                size_t o = (((size_t)b * NH + h) * LEN + lst[jj]) * DK + k;
                K[o] = acc0[j];
                V[o] = acc1[j];
            }
        }
        __syncthreads();
    }
}

// ---------------------------------------------------------------------------
// Kernel B: intent projections (Q), same pipelining.
// ---------------------------------------------------------------------------
__global__ __launch_bounds__(256, 3)
void proj_intent_kernel(const float* __restrict__ intent,
                        const int*   __restrict__ b_seq2,
                        const float* __restrict__ W)
{
    int b = blockIdx.y, t = blockIdx.x, tid = threadIdx.x;
    __shared__ float xs[TILE][DM];
    __shared__ int   lst[NIS];
    __shared__ int   s_cnt;

    if (tid == 0) s_cnt = 0;
    __syncthreads();
    for (int n = tid; n < NIS; n += 256)
        if (b_seq2[b * NIS + n] == t) { int p = atomicAdd(&s_cnt, 1); lst[p] = n; }
    __syncthreads();
    int ntok   = s_cnt;
    int ntiles = (ntok + TILE - 1) / TILE;

    const float* wp = W + (size_t)t * DM * DM + tid;   // W_intent[0][t][d][o]
    int h = tid >> 6, k = tid & 63;

    for (int tile = 0; tile < ntiles; ++tile) {
        int tb = tile * TILE;
#pragma unroll
        for (int j = 0; j < TILE; ++j) {
            int jj = tb + j;
            float v = 0.0f;
            if (jj < ntok) v = intent[(size_t)lst[jj] * DM + tid];
            xs[j][tid] = v;
        }
        __syncthreads();

        float acc[TILE];
#pragma unroll
        for (int j = 0; j < TILE; ++j) acc[j] = 0.0f;

        float a0 = wp[0 * DM], a1 = wp[1 * DM], a2 = wp[2 * DM], a3 = wp[3 * DM];
        for (int d4 = 0; d4 < DM / 4; ++d4) {
            int dn = (d4 + 1 < DM / 4) ? (d4 + 1) * 4 : 0;
            float na0 = wp[(dn + 0) * DM], na1 = wp[(dn + 1) * DM];
            float na2 = wp[(dn + 2) * DM], na3 = wp[(dn + 3) * DM];
            int d = d4 * 4;
#pragma unroll
            for (int j = 0; j < TILE; ++j) {
                float4 xv = *reinterpret_cast<const float4*>(&xs[j][d]);
                acc[j] = fmaf(xv.w, a3, fmaf(xv.z, a2, fmaf(xv.y, a1, fmaf(xv.x, a0, acc[j]))));
            }
            a0 = na0; a1 = na1; a2 = na2; a3 = na3;
        }
#pragma unroll
        for (int j = 0; j < TILE; ++j) {
            int jj = tb + j;
            if (jj < ntok)
                g_Q[(((size_t)b * NH + h) * NIS + lst[jj]) * DK + k] = acc[j];
        }
        __syncthreads();
    }
}

// ---------------------------------------------------------------------------
// Kernel C: attention. One block per (b,h). 2 queries/thread in score phase
// (each K smem read feeds 50 FMAs). Phases: Bs scores (4x64q) -> Ba scores
// (32q) -> Bs sparse output -> Ba sparse output; K/V share one smem buffer,
// top-k results for all 288 queries parked in smem between phases.
// ---------------------------------------------------------------------------
__device__ __forceinline__ void mask_scale(float (&p)[25], const int* __restrict__ mrow)
{
#pragma unroll
    for (int i = 0; i < 25; ++i) {
        float s = p[i] * 0.125f;               // / sqrt(64)
        if (mrow[i] == 0) s = -1e30f;
        p[i] = s;
    }
}

__device__ __forceinline__ void softmax_topk(float (&p)[25], int g, int nb, int kk,
                                             int qg, float* keptP, int* keptI)
{
    float mx = -3.4e38f;
#pragma unroll
    for (int i = 0; i < 25; ++i) mx = fmaxf(mx, p[i]);
#pragma unroll
    for (int off = 1; off < 8; off <<= 1)
        mx = fmaxf(mx, __shfl_xor_sync(0xffffffffu, mx, off));
    float sum = 0.0f;
#pragma unroll
    for (int i = 0; i < 25; ++i) { float e = expf(p[i] - mx); p[i] = e; sum += e; }
#pragma unroll
    for (int off = 1; off < 8; off <<= 1)
        sum += __shfl_xor_sync(0xffffffffu, sum, off);
    float inv = 1.0f / sum;
#pragma unroll
    for (int i = 0; i < 25; ++i) p[i] *= inv;

    for (int it = 0; it < kk; ++it) {
        float bv = -2.0f; int bi = 0x40000000;
#pragma unroll
        for (int i = 0; i < 25; ++i) {
            if (p[i] > bv) { bv = p[i]; bi = nb + i; }     // strict > keeps earliest idx
        }
#pragma unroll
        for (int off = 1; off < 8; off <<= 1) {
            float ov = __shfl_xor_sync(0xffffffffu, bv, off);
            int   oi = __shfl_xor_sync(0xffffffffu, bi, off);
            if (ov > bv || (ov == bv && oi < bi)) { bv = ov; bi = oi; }
        }
#pragma unroll
        for (int i = 0; i < 25; ++i)
            if (nb + i == bi) p[i] = -1.0f;                // predicated removal
        if (g == 0) { keptP[qg * 12 + it] = bv; keptI[qg * 12 + it] = bi; }
    }
}

__global__ __launch_bounds__(256, 2)
void attn_kernel(const int* __restrict__ mask,
                 const int* __restrict__ type_cnt,
                 float* __restrict__ out)
{
    extern __shared__ float sm[];
    float* KV    = sm;                       // [64][200] as K^T, then [200][64] as V
    float* Qs    = KV + 64 * LEN;            // [64][65] padded
    float* keptP = Qs + 64 * 65;             // [288][12]
    int*   keptI = (int*)(keptP + NIS * 12); // [288][12]
    __shared__ int skk[9];

    int bh = blockIdx.x;
    int b = bh >> 2, h = bh & 3;
    int tid = threadIdx.x;
    int g = tid & 7, qpair = tid >> 3;
    int nb = g * 25;

    if (tid < 9) {
        int v;
        if (tid < 8) v = type_cnt[b * 9 + 1 + tid];
        else { v = 0; for (int i = 0; i < 9; ++i) v += type_cnt[b * 9 + i]; }
        skk[tid] = (int)get_cn((float)v);
    }

    const size_t bhoff = ((size_t)(b * NH + h)) * LEN * DK;
    const size_t qoff  = ((size_t)(b * NH + h)) * NIS * DK;

    // ---- Bs scores ----
    {
        const float* Ksrc = g_Kbs + bhoff;
        for (int idx = tid; idx < LEN * DK; idx += 256) {
            int n = idx >> 6, k = idx & 63;
            KV[k * LEN + n] = Ksrc[idx];
        }
    }
    __syncthreads();

    for (int pass = 0; pass < 4; ++pass) {
        int qb = pass * 64;
        for (int idx = tid; idx < 64 * DK; idx += 256) {
            int q = idx >> 6, k = idx & 63;
            Qs[q * 65 + k] = g_Q[qoff + (size_t)(qb + q) * DK + k];
        }
        __syncthreads();

        float p0[25], p1[25];
#pragma unroll
        for (int i = 0; i < 25; ++i) { p0[i] = 0.0f; p1[i] = 0.0f; }
        const float* qrow0 = &Qs[qpair * 65];
        const float* qrow1 = &Qs[(qpair + 32) * 65];
        for (int k = 0; k < DK; ++k) {
            float qv0 = qrow0[k], qv1 = qrow1[k];
            const float* kr = &KV[k * LEN + nb];
#pragma unroll
            for (int i = 0; i < 25; ++i) {
                float kv = kr[i];
                p0[i] = fmaf(qv0, kv, p0[i]);
                p1[i] = fmaf(qv1, kv, p1[i]);
            }
        }
        int q0 = qb + qpair, q1 = q0 + 32;
        mask_scale(p0, mask + ((size_t)b * NIS + q0) * LEN + nb);
        mask_scale(p1, mask + ((size_t)b * NIS + q1) * LEN + nb);
        softmax_topk(p0, g, nb, skk[q0 >> 5], q0, keptP, keptI);
        softmax_topk(p1, g, nb, skk[q1 >> 5], q1, keptP, keptI);
        __syncthreads();
    }

    // ---- Ba scores ----
    {
        const float* Ksrc = g_Kba + bhoff;
        for (int idx = tid; idx < LEN * DK; idx += 256) {
            int n = idx >> 6, k = idx & 63;
            KV[k * LEN + n] = Ksrc[idx];
        }
        for (int idx = tid; idx < 32 * DK; idx += 256) {
            int q = idx >> 6, k = idx & 63;
            Qs[q * 65 + k] = g_Q[qoff + (size_t)(256 + q) * DK + k];
        }
    }
    __syncthreads();
    {
        float p0[25];
#pragma unroll
        for (int i = 0; i < 25; ++i) p0[i] = 0.0f;
        const float* qrow0 = &Qs[qpair * 65];
        for (int k = 0; k < DK; ++k) {
            float qv0 = qrow0[k];
            const float* kr = &KV[k * LEN + nb];
#pragma unroll
            for (int i = 0; i < 25; ++i) p0[i] = fmaf(qv0, kr[i], p0[i]);
        }
        int q0 = 256 + qpair;
        mask_scale(p0, mask + ((size_t)b * NIS + q0) * LEN + nb);
        softmax_topk(p0, g, nb, skk[8], q0, keptP, keptI);
    }
    __syncthreads();

    // ---- Bs sparse output ----
    {
        const float* Vsrc = g_Vbs + bhoff;
        for (int idx = tid; idx < LEN * DK; idx += 256) KV[idx] = Vsrc[idx];
    }
    __syncthreads();
    int qloc = tid >> 3, d0 = (tid & 7) * 8;
    for (int pass = 0; pass < 8; ++pass) {
        int q = pass * 32 + qloc;
        int kk = skk[q >> 5];
        float4 o0 = {0, 0, 0, 0}, o1 = {0, 0, 0, 0};
        for (int j = 0; j < kk; ++j) {
            float pv = keptP[q * 12 + j];
            int   n  = keptI[q * 12 + j];
            const float4* vr = reinterpret_cast<const float4*>(&KV[n * DK + d0]);
            float4 v0 = vr[0], v1 = vr[1];
            o0.x = fmaf(pv, v0.x, o0.x); o0.y = fmaf(pv, v0.y, o0.y);
            o0.z = fmaf(pv, v0.z, o0.z); o0.w = fmaf(pv, v0.w, o0.w);
            o1.x = fmaf(pv, v1.x, o1.x); o1.y = fmaf(pv, v1.y, o1.y);
            o1.z = fmaf(pv, v1.z, o1.z); o1.w = fmaf(pv, v1.w, o1.w);
        }
        float* orow = out + ((size_t)b * NIS + q) * (NH * DK) + h * DK + d0;
        reinterpret_cast<float4*>(orow)[0] = o0;
        reinterpret_cast<float4*>(orow)[1] = o1;
    }
    __syncthreads();

    // ---- Ba sparse output ----
    {
        const float* Vsrc = g_Vba + bhoff;
        for (int idx = tid; idx < LEN * DK; idx += 256) KV[idx] = Vsrc[idx];
    }
    __syncthreads();
    {
        int q = 256 + qloc;
        int kk = skk[8];
        float4 o0 = {0, 0, 0, 0}, o1 = {0, 0, 0, 0};
        for (int j = 0; j < kk; ++j) {
            float pv = keptP[q * 12 + j];
            int   n  = keptI[q * 12 + j];
            const float4* vr = reinterpret_cast<const float4*>(&KV[n * DK + d0]);
            float4 v0 = vr[0], v1 = vr[1];
            o0.x = fmaf(pv, v0.x, o0.x); o0.y = fmaf(pv, v0.y, o0.y);
            o0.z = fmaf(pv, v0.z, o0.z); o0.w = fmaf(pv, v0.w, o0.w);
            o1.x = fmaf(pv, v1.x, o1.x); o1.y = fmaf(pv, v1.y, o1.y);
            o1.z = fmaf(pv, v1.z, o1.z); o1.w = fmaf(pv, v1.w, o1.w);
        }
        float* orow = out + ((size_t)b * NIS + q) * (NH * DK) + h * DK + d0;
        reinterpret_cast<float4*>(orow)[0] = o0;
        reinterpret_cast<float4*>(orow)[1] = o1;
    }
}

// ---------------------------------------------------------------------------
static const int ATTN_SMEM = (64 * LEN + 64 * 65 + NIS * 12) * 4 + NIS * 12 * 4;

extern "C" void kernel_launch(void* const* d_in, const int* in_sizes, int n_in,
                              void* d_out, int out_size)
{
    const float* item     = (const float*)d_in[0];
    const float* intent   = (const float*)d_in[1];
    const int*   mask     = (const int*)  d_in[2];
    const int*   b_seq    = (const int*)  d_in[3];
    const int*   b_seq2   = (const int*)  d_in[4];
    const int*   type_cnt = (const int*)  d_in[5];
    const float* W_item   = (const float*)d_in[6];
    const float* W_intent = (const float*)d_in[7];
    float* out = (float*)d_out;

    cudaFuncSetAttribute(attn_kernel, cudaFuncAttributeMaxDynamicSharedMemorySize, ATTN_SMEM);

    proj_item_kernel  <<<dim3(NTI + (LEN + TILE - 1) / TILE, NBATCH), 256>>>(item, b_seq, W_item);
    proj_intent_kernel<<<dim3(NTQ, NBATCH), 256>>>(intent, b_seq2, W_intent);
    attn_kernel       <<<NBATCH * NH, 256, ATTN_SMEM>>>(mask, type_cnt, out);
}

// round 7
// speedup vs baseline: 1.6094x; 1.3447x over previous
#include <cuda_runtime.h>
#include <math.h>
#include <stdint.h>

#define NBATCH 256
#define LEN    200
#define DM     256
#define NH     4
#define DK     64
#define NIS    288
#define NTI    10   // item weight types
#define NTQ    9    // intent weight types

#define NTOK_I (NBATCH * LEN)   // 51200
#define NTOK_Q (NBATCH * NIS)   // 73728
#define CAPI   8192             // per-type capacity (avg 5120)
#define CAPQ   12288            // per-type capacity (avg 8192)
#define MT     64               // M rows per block tile
#define XPAD   260              // smem row stride (conflict-free fragment LDS)

// ---------------- scratch (static device globals; no allocation) ------------
__device__ float g_Kbs[(size_t)NBATCH * NH * LEN * DK];
__device__ float g_Vbs[(size_t)NBATCH * NH * LEN * DK];
__device__ float g_Kba[(size_t)NBATCH * NH * LEN * DK];
__device__ float g_Vba[(size_t)NBATCH * NH * LEN * DK];
__device__ float g_Q  [(size_t)NBATCH * NH * NIS * DK];

__device__ int   g_cntI[NTI];
__device__ int   g_cntQ[NTQ];
__device__ int   g_listI[NTI * CAPI];
__device__ int   g_listQ[NTQ * CAPQ];
// fragment-swizzled weights: [t][nsub][ksub][lane] -> {b0_hi,b1_hi,b0_lo,b1_lo}
__device__ uint4 g_WfI[NTI * 64 * 32 * 32];   // item: N=512 -> 64 nsub
__device__ uint4 g_WfQ[NTQ * 32 * 32 * 32];   // intent: N=256 -> 32 nsub

// ---------------- helpers ---------------------------------------------------
__device__ __forceinline__ unsigned f2tf(float x) {
    unsigned r;
    asm("cvt.rna.tf32.f32 %0, %1;" : "=r"(r) : "f"(x));
    return r;
}

__device__ __forceinline__ void mma8(float* d,
                                     unsigned a0, unsigned a1, unsigned a2, unsigned a3,
                                     unsigned b0, unsigned b1) {
    asm("mma.sync.aligned.m16n8k8.row.col.f32.tf32.tf32.f32 "
        "{%0,%1,%2,%3},{%4,%5,%6,%7},{%8,%9},{%0,%1,%2,%3};"
        : "+f"(d[0]), "+f"(d[1]), "+f"(d[2]), "+f"(d[3])
        : "r"(a0), "r"(a1), "r"(a2), "r"(a3), "r"(b0), "r"(b1));
}

__device__ __forceinline__ float get_cn(float xf) {
    const float quarter = 24.0f / 4.0f;            // 6
    float safe = fmaxf(xf, quarter);
    float f1 = quarter + floorf(logf(4.0f * safe / 24.0f) /
                                logf(4.0f * 200.0f / 24.0f) * quarter);
    float upper = 24.0f / 2.0f - 1.0f;             // 11
    return (xf < quarter) ? xf : fminf(f1, upper);
}

// ---------------- setup kernels ---------------------------------------------
__global__ void zero_cnt_kernel() {
    int t = threadIdx.x;
    if (t < NTI) g_cntI[t] = 0;
    if (t < NTQ) g_cntQ[t] = 0;
}

__global__ void build_lists_kernel(const int* __restrict__ b_seq,
                                   const int* __restrict__ b_seq2) {
    int i = blockIdx.x * 256 + threadIdx.x;
    if (i < NTOK_I) {
        int t = b_seq[i];                       // 0..9
        if (t >= 0 && t < NTI) {
            int p = atomicAdd(&g_cntI[t], 1);
            if (p < CAPI) g_listI[t * CAPI + p] = i;
        }
    }
    if (i < NTOK_Q) {
        int t = b_seq2[i];                      // 0..8
        if (t >= 0 && t < NTQ) {
            int p = atomicAdd(&g_cntQ[t], 1);
            if (p < CAPQ) g_listQ[t * CAPQ + p] = i;
        }
    }
}

// item weights -> swizzled hi/lo fragments. idx = ((t*64+ns)*32+ks)*32+lane
__global__ void wfrag_item_kernel(const float* __restrict__ W) {
    int idx = blockIdx.x * 256 + threadIdx.x;
    if (idx >= NTI * 64 * 32 * 32) return;
    int lane = idx & 31, ks = (idx >> 5) & 31, ns = (idx >> 10) & 63, t = idx >> 16;
    int n = ns * 8 + (lane >> 2);
    int k = ks * 8 + (lane & 3);
    int m = (n < 256) ? 0 : 1;
    int c = n & 255;
    const float* Wm = W + ((size_t)(m * NTI + t)) * DM * DM;
    float w0 = Wm[k * DM + c];
    float w1 = Wm[(k + 4) * DM + c];
    unsigned h0 = f2tf(w0), h1 = f2tf(w1);
    unsigned l0 = f2tf(w0 - __uint_as_float(h0));
    unsigned l1 = f2tf(w1 - __uint_as_float(h1));
    g_WfI[idx] = make_uint4(h0, h1, l0, l1);
}

// intent weights. idx = ((t*32+ns)*32+ks)*32+lane
__global__ void wfrag_q_kernel(const float* __restrict__ W) {
    int idx = blockIdx.x * 256 + threadIdx.x;
    if (idx >= NTQ * 32 * 32 * 32) return;
    int lane = idx & 31, ks = (idx >> 5) & 31, ns = (idx >> 10) & 31, t = idx >> 15;
    int n = ns * 8 + (lane >> 2);
    int k = ks * 8 + (lane & 3);
    const float* Wm = W + (size_t)t * DM * DM;
    float w0 = Wm[k * DM + n];
    float w1 = Wm[(k + 4) * DM + n];
    unsigned h0 = f2tf(w0), h1 = f2tf(w1);
    unsigned l0 = f2tf(w0 - __uint_as_float(h0));
    unsigned l1 = f2tf(w1 - __uint_as_float(h1));
    g_WfQ[idx] = make_uint4(h0, h1, l0, l1);
}

// ---------------------------------------------------------------------------
// Item projection GEMM: C[64 x 512] = X[64 x 256] * Wcat[256 x 512], 4xTF32
// (full fp32-accuracy decomposition: ah*bh + ah*bl + al*bh + al*bl).
// 8 warps = 4(m) x 2(n); 2 n-passes; cols 0..255 -> K, 256..511 -> V.
// useList=1: gather rows from g_listI[blockIdx.y], write g_Kbs/g_Vbs.
// useList=0: identity rows, type 9, write g_Kba/g_Vba.
// ---------------------------------------------------------------------------
__global__ __launch_bounds__(256, 2)
void proj_item_mma(const float* __restrict__ item, int useList)
{
    int t, count;
    const int* list;
    float* outK;
    float* outV;
    if (useList) {
        t = blockIdx.y;
        count = min(g_cntI[t], CAPI);
        list = g_listI + t * CAPI;
        outK = g_Kbs; outV = g_Vbs;
    } else {
        t = NTI - 1;
        count = NTOK_I;
        list = nullptr;
        outK = g_Kba; outV = g_Vba;
    }
    int row0 = blockIdx.x * MT;
    if (row0 >= count) return;

    extern __shared__ float xs[];              // [MT][XPAD]
    __shared__ int stok[MT];
    int tid = threadIdx.x;

    if (tid < MT) {
        int gr = row0 + tid;
        stok[tid] = (gr < count) ? (list ? list[gr] : gr) : -1;
    }
    __syncthreads();

    // load A tile (64 x 256)
    {
        int r = tid >> 2, q4 = tid & 3;
        int tok = stok[r];
        const float* src = item + (size_t)max(tok, 0) * DM;
#pragma unroll
        for (int i = 0; i < 16; ++i) {
            int qd = q4 + i * 4;
            float4 v = make_float4(0.f, 0.f, 0.f, 0.f);
            if (tok >= 0) v = reinterpret_cast<const float4*>(src)[qd];
            *reinterpret_cast<float4*>(&xs[r * XPAD + qd * 4]) = v;
        }
    }
    __syncthreads();

    int wid = tid >> 5, lane = tid & 31;
    int wm = wid >> 1, wn = wid & 1;
    int la = lane >> 2, lb = lane & 3;
    const float* xa = &xs[(wm * 16 + la) * XPAD];
    const float* xb = xa + 8 * XPAD;

    // store-address precompute for this thread's two rows
    int gra = row0 + wm * 16 + la, grb = gra + 8;
    int toka = (gra < count) ? (list ? list[gra] : gra) : -1;
    int tokb = (grb < count) ? (list ? list[grb] : grb) : -1;
    int ba_ = (toka >= 0) ? toka / LEN : 0, na_ = (toka >= 0) ? toka % LEN : 0;
    int bb_ = (tokb >= 0) ? tokb / LEN : 0, nb_ = (tokb >= 0) ? tokb % LEN : 0;

    for (int pass = 0; pass < 2; ++pass) {
        int nsb = (pass * 2 + wn) * 16;        // nsub base (0,16,32,48)
        const uint4* wf = g_WfI + (((size_t)t * 64 + nsb) * 32) * 32 + lane;

        float acc[16][4];
#pragma unroll
        for (int ns = 0; ns < 16; ++ns)
#pragma unroll
            for (int j = 0; j < 4; ++j) acc[ns][j] = 0.0f;

        for (int ks = 0; ks < 32; ++ks) {
            int k0 = ks * 8;
            float f0 = xa[k0 + lb],     f1 = xb[k0 + lb];
            float f2 = xa[k0 + lb + 4], f3 = xb[k0 + lb + 4];
            unsigned ah0 = f2tf(f0), ah1 = f2tf(f1), ah2 = f2tf(f2), ah3 = f2tf(f3);
            unsigned al0 = f2tf(f0 - __uint_as_float(ah0));
            unsigned al1 = f2tf(f1 - __uint_as_float(ah1));
            unsigned al2 = f2tf(f2 - __uint_as_float(ah2));
            unsigned al3 = f2tf(f3 - __uint_as_float(ah3));
            const uint4* wfk = wf + ks * 32;
#pragma unroll
            for (int ns = 0; ns < 16; ++ns) {
                uint4 w = wfk[(size_t)ns * 1024];
                mma8(acc[ns], al0, al1, al2, al3, w.z, w.w);   // al*bl (smallest first)
                mma8(acc[ns], ah0, ah1, ah2, ah3, w.z, w.w);   // ah*bl
                mma8(acc[ns], al0, al1, al2, al3, w.x, w.y);   // al*bh
                mma8(acc[ns], ah0, ah1, ah2, ah3, w.x, w.y);   // ah*bh
            }
        }

#pragma unroll
        for (int ns = 0; ns < 16; ++ns) {
            int cg = (nsb + ns) * 8 + lb * 2;
            int mat = cg >> 8, hh = (cg >> 6) & 3, kd = cg & 63;
            float* base = mat ? outV : outK;
            if (toka >= 0) {
                float2 v = make_float2(acc[ns][0], acc[ns][1]);
                *reinterpret_cast<float2*>(
                    &base[(((size_t)ba_ * NH + hh) * LEN + na_) * DK + kd]) = v;
            }
            if (tokb >= 0) {
                float2 v = make_float2(acc[ns][2], acc[ns][3]);
                *reinterpret_cast<float2*>(
                    &base[(((size_t)bb_ * NH + hh) * LEN + nb_) * DK + kd]) = v;
            }
        }
        __syncthreads();
    }
}

// ---------------------------------------------------------------------------
// Intent projection GEMM: C[64 x 256] = X[64 x 256] * W[256 x 256], 4xTF32.
// blockIdx.y = type t; rows gathered from g_listQ. Input row = token % NIS.
// ---------------------------------------------------------------------------
__global__ __launch_bounds__(256, 2)
void proj_q_mma(const float* __restrict__ intent)
{
    int t = blockIdx.y;
    int count = min(g_cntQ[t], CAPQ);
    const int* list = g_listQ + t * CAPQ;
    int row0 = blockIdx.x * MT;
    if (row0 >= count) return;

    extern __shared__ float xs[];              // [MT][XPAD]
    __shared__ int stok[MT];
    int tid = threadIdx.x;

    if (tid < MT) {
        int gr = row0 + tid;
        stok[tid] = (gr < count) ? list[gr] : -1;
    }
    __syncthreads();

    {
        int r = tid >> 2, q4 = tid & 3;
        int tok = stok[r];
        const float* src = intent + (size_t)((tok >= 0 ? tok : 0) % NIS) * DM;
#pragma unroll
        for (int i = 0; i < 16; ++i) {
            int qd = q4 + i * 4;
            float4 v = make_float4(0.f, 0.f, 0.f, 0.f);
            if (tok >= 0) v = reinterpret_cast<const float4*>(src)[qd];
            *reinterpret_cast<float4*>(&xs[r * XPAD + qd * 4]) = v;
        }
    }
    __syncthreads();

    int wid = tid >> 5, lane = tid & 31;
    int wm = wid >> 1, wn = wid & 1;
    int la = lane >> 2, lb = lane & 3;
    const float* xa = &xs[(wm * 16 + la) * XPAD];
    const float* xb = xa + 8 * XPAD;

    int gra = row0 + wm * 16 + la, grb = gra + 8;
    int toka = (gra < count) ? list[gra] : -1;
    int tokb = (grb < count) ? list[grb] : -1;
    int ba_ = (toka >= 0) ? toka / NIS : 0, qa_ = (toka >= 0) ? toka % NIS : 0;
    int bb_ = (tokb >= 0) ? tokb / NIS : 0, qb_ = (tokb >= 0) ? tokb % NIS : 0;

    int nsb = wn * 16;
    const uint4* wf = g_WfQ + (((size_t)t * 32 + nsb) * 32) * 32 + lane;

    float acc[16][4];
#pragma unroll
    for (int ns = 0; ns < 16; ++ns)
#pragma unroll
        for (int j = 0; j < 4; ++j) acc[ns][j] = 0.0f;

    for (int ks = 0; ks < 32; ++ks) {
        int k0 = ks * 8;
        float f0 = xa[k0 + lb],     f1 = xb[k0 + lb];
        float f2 = xa[k0 + lb + 4], f3 = xb[k0 + lb + 4];
        unsigned ah0 = f2tf(f0), ah1 = f2tf(f1), ah2 = f2tf(f2), ah3 = f2tf(f3);
        unsigned al0 = f2tf(f0 - __uint_as_float(ah0));
        unsigned al1 = f2tf(f1 - __uint_as_float(ah1));
        unsigned al2 = f2tf(f2 - __uint_as_float(ah2));
        unsigned al3 = f2tf(f3 - __uint_as_float(ah3));
        const uint4* wfk = wf + ks * 32;
#pragma unroll
        for (int ns = 0; ns < 16; ++ns) {
            uint4 w = wfk[(size_t)ns * 1024];
            mma8(acc[ns], al0, al1, al2, al3, w.z, w.w);   // al*bl
            mma8(acc[ns], ah0, ah1, ah2, ah3, w.z, w.w);   // ah*bl
            mma8(acc[ns], al0, al1, al2, al3, w.x, w.y);   // al*bh
            mma8(acc[ns], ah0, ah1, ah2, ah3, w.x, w.y);   // ah*bh
        }
    }

#pragma unroll
    for (int ns = 0; ns < 16; ++ns) {
        int cg = (nsb + ns) * 8 + lb * 2;
        int hh = cg >> 6, kd = cg & 63;
        if (toka >= 0) {
            float2 v = make_float2(acc[ns][0], acc[ns][1]);
            *reinterpret_cast<float2*>(
                &g_Q[(((size_t)ba_ * NH + hh) * NIS + qa_) * DK + kd]) = v;
        }
        if (tokb >= 0) {
            float2 v = make_float2(acc[ns][2], acc[ns][3]);
            *reinterpret_cast<float2*>(
                &g_Q[(((size_t)bb_ * NH + hh) * NIS + qb_) * DK + kd]) = v;
        }
    }
}

// ---------------------------------------------------------------------------
// Attention (unchanged): scores + softmax + top-k + sparse p@V.
// ---------------------------------------------------------------------------
__device__ __forceinline__ void mask_scale(float (&p)[25], const int* __restrict__ mrow)
{
#pragma unroll
    for (int i = 0; i < 25; ++i) {
        float s = p[i] * 0.125f;
        if (mrow[i] == 0) s = -1e30f;
        p[i] = s;
    }
}

__device__ __forceinline__ void softmax_topk(float (&p)[25], int g, int nb, int kk,
                                             int qg, float* keptP, int* keptI)
{
    float mx = -3.4e38f;
#pragma unroll
    for (int i = 0; i < 25; ++i) mx = fmaxf(mx, p[i]);
#pragma unroll
    for (int off = 1; off < 8; off <<= 1)
        mx = fmaxf(mx, __shfl_xor_sync(0xffffffffu, mx, off));
    float sum = 0.0f;
#pragma unroll
    for (int i = 0; i < 25; ++i) { float e = expf(p[i] - mx); p[i] = e; sum += e; }
#pragma unroll
    for (int off = 1; off < 8; off <<= 1)
        sum += __shfl_xor_sync(0xffffffffu, sum, off);
    float inv = 1.0f / sum;
#pragma unroll
    for (int i = 0; i < 25; ++i) p[i] *= inv;

    for (int it = 0; it < kk; ++it) {
        float bv = -2.0f; int bi = 0x40000000;
#pragma unroll
        for (int i = 0; i < 25; ++i) {
            if (p[i] > bv) { bv = p[i]; bi = nb + i; }
        }
#pragma unroll
        for (int off = 1; off < 8; off <<= 1) {
            float ov = __shfl_xor_sync(0xffffffffu, bv, off);
            int   oi = __shfl_xor_sync(0xffffffffu, bi, off);
            if (ov > bv || (ov == bv && oi < bi)) { bv = ov; bi = oi; }
        }
#pragma unroll
        for (int i = 0; i < 25; ++i)
            if (nb + i == bi) p[i] = -1.0f;
        if (g == 0) { keptP[qg * 12 + it] = bv; keptI[qg * 12 + it] = bi; }
    }
}

__global__ __launch_bounds__(256, 2)
void attn_kernel(const int* __restrict__ mask,
                 const int* __restrict__ type_cnt,
                 float* __restrict__ out)
{
    extern __shared__ float sm[];
    float* KV    = sm;
    float* Qs    = KV + 64 * LEN;
    float* keptP = Qs + 64 * 65;
    int*   keptI = (int*)(keptP + NIS * 12);
    __shared__ int skk[9];

    int bh = blockIdx.x;
    int b = bh >> 2, h = bh & 3;
    int tid = threadIdx.x;
    int g = tid & 7, qpair = tid >> 3;
    int nb = g * 25;

    if (tid < 9) {
        int v;
        if (tid < 8) v = type_cnt[b * 9 + 1 + tid];
        else { v = 0; for (int i = 0; i < 9; ++i) v += type_cnt[b * 9 + i]; }
        skk[tid] = (int)get_cn((float)v);
    }

    const size_t bhoff = ((size_t)(b * NH + h)) * LEN * DK;
    const size_t qoff  = ((size_t)(b * NH + h)) * NIS * DK;

    {
        const float* Ksrc = g_Kbs + bhoff;
        for (int idx = tid; idx < LEN * DK; idx += 256) {
            int n = idx >> 6, k = idx & 63;
            KV[k * LEN + n] = Ksrc[idx];
        }
    }
    __syncthreads();

    for (int pass = 0; pass < 4; ++pass) {
        int qb = pass * 64;
        for (int idx = tid; idx < 64 * DK; idx += 256) {
            int q = idx >> 6, k = idx & 63;
            Qs[q * 65 + k] = g_Q[qoff + (size_t)(qb + q) * DK + k];
        }
        __syncthreads();

        float p0[25], p1[25];
#pragma unroll
        for (int i = 0; i < 25; ++i) { p0[i] = 0.0f; p1[i] = 0.0f; }
        const float* qrow0 = &Qs[qpair * 65];
        const float* qrow1 = &Qs[(qpair + 32) * 65];
        for (int k = 0; k < DK; ++k) {
            float qv0 = qrow0[k], qv1 = qrow1[k];
            const float* kr = &KV[k * LEN + nb];
#pragma unroll
            for (int i = 0; i < 25; ++i) {
                float kv = kr[i];
                p0[i] = fmaf(qv0, kv, p0[i]);
                p1[i] = fmaf(qv1, kv, p1[i]);
            }
        }
        int q0 = qb + qpair, q1 = q0 + 32;
        mask_scale(p0, mask + ((size_t)b * NIS + q0) * LEN + nb);
        mask_scale(p1, mask + ((size_t)b * NIS + q1) * LEN + nb);
        softmax_topk(p0, g, nb, skk[q0 >> 5], q0, keptP, keptI);
        softmax_topk(p1, g, nb, skk[q1 >> 5], q1, keptP, keptI);
        __syncthreads();
    }

    {
        const float* Ksrc = g_Kba + bhoff;
        for (int idx = tid; idx < LEN * DK; idx += 256) {
            int n = idx >> 6, k = idx & 63;
            KV[k * LEN + n] = Ksrc[idx];
        }
        for (int idx = tid; idx < 32 * DK; idx += 256) {
            int q = idx >> 6, k = idx & 63;
            Qs[q * 65 + k] = g_Q[qoff + (size_t)(256 + q) * DK + k];
        }
    }
    __syncthreads();
    {
        float p0[25];
#pragma unroll
        for (int i = 0; i < 25; ++i) p0[i] = 0.0f;
        const float* qrow0 = &Qs[qpair * 65];
        for (int k = 0; k < DK; ++k) {
            float qv0 = qrow0[k];
            const float* kr = &KV[k * LEN + nb];
#pragma unroll
            for (int i = 0; i < 25; ++i) p0[i] = fmaf(qv0, kr[i], p0[i]);
        }
        int q0 = 256 + qpair;
        mask_scale(p0, mask + ((size_t)b * NIS + q0) * LEN + nb);
        softmax_topk(p0, g, nb, skk[8], q0, keptP, keptI);
    }
    __syncthreads();

    {
        const float* Vsrc = g_Vbs + bhoff;
        for (int idx = tid; idx < LEN * DK; idx += 256) KV[idx] = Vsrc[idx];
    }
    __syncthreads();
    int qloc = tid >> 3, d0 = (tid & 7) * 8;
    for (int pass = 0; pass < 8; ++pass) {
        int q = pass * 32 + qloc;
        int kk = skk[q >> 5];
        float4 o0 = {0, 0, 0, 0}, o1 = {0, 0, 0, 0};
        for (int j = 0; j < kk; ++j) {
            float pv = keptP[q * 12 + j];
            int   n  = keptI[q * 12 + j];
            const float4* vr = reinterpret_cast<const float4*>(&KV[n * DK + d0]);
            float4 v0 = vr[0], v1 = vr[1];
            o0.x = fmaf(pv, v0.x, o0.x); o0.y = fmaf(pv, v0.y, o0.y);
            o0.z = fmaf(pv, v0.z, o0.z); o0.w = fmaf(pv, v0.w, o0.w);
            o1.x = fmaf(pv, v1.x, o1.x); o1.y = fmaf(pv, v1.y, o1.y);
            o1.z = fmaf(pv, v1.z, o1.z); o1.w = fmaf(pv, v1.w, o1.w);
        }
        float* orow = out + ((size_t)b * NIS + q) * (NH * DK) + h * DK + d0;
        reinterpret_cast<float4*>(orow)[0] = o0;
        reinterpret_cast<float4*>(orow)[1] = o1;
    }
    __syncthreads();

    {
        const float* Vsrc = g_Vba + bhoff;
        for (int idx = tid; idx < LEN * DK; idx += 256) KV[idx] = Vsrc[idx];
    }
    __syncthreads();
    {
        int q = 256 + qloc;
        int kk = skk[8];
        float4 o0 = {0, 0, 0, 0}, o1 = {0, 0, 0, 0};
        for (int j = 0; j < kk; ++j) {
            float pv = keptP[q * 12 + j];
            int   n  = keptI[q * 12 + j];
            const float4* vr = reinterpret_cast<const float4*>(&KV[n * DK + d0]);
            float4 v0 = vr[0], v1 = vr[1];
            o0.x = fmaf(pv, v0.x, o0.x); o0.y = fmaf(pv, v0.y, o0.y);
            o0.z = fmaf(pv, v0.z, o0.z); o0.w = fmaf(pv, v0.w, o0.w);
            o1.x = fmaf(pv, v1.x, o1.x); o1.y = fmaf(pv, v1.y, o1.y);
            o1.z = fmaf(pv, v1.z, o1.z); o1.w = fmaf(pv, v1.w, o1.w);
        }
        float* orow = out + ((size_t)b * NIS + q) * (NH * DK) + h * DK + d0;
        reinterpret_cast<float4*>(orow)[0] = o0;
        reinterpret_cast<float4*>(orow)[1] = o1;
    }
}

// ---------------------------------------------------------------------------
static const int ATTN_SMEM = (64 * LEN + 64 * 65 + NIS * 12) * 4 + NIS * 12 * 4;
static const int PROJ_SMEM = MT * XPAD * 4;   // 66560 B

extern "C" void kernel_launch(void* const* d_in, const int* in_sizes, int n_in,
                              void* d_out, int out_size)
{
    const float* item     = (const float*)d_in[0];
    const float* intent   = (const float*)d_in[1];
    const int*   mask     = (const int*)  d_in[2];
    const int*   b_seq    = (const int*)  d_in[3];
    const int*   b_seq2   = (const int*)  d_in[4];
    const int*   type_cnt = (const int*)  d_in[5];
    const float* W_item   = (const float*)d_in[6];
    const float* W_intent = (const float*)d_in[7];
    float* out = (float*)d_out;

    cudaFuncSetAttribute(attn_kernel,    cudaFuncAttributeMaxDynamicSharedMemorySize, ATTN_SMEM);
    cudaFuncSetAttribute(proj_item_mma,  cudaFuncAttributeMaxDynamicSharedMemorySize, PROJ_SMEM);
    cudaFuncSetAttribute(proj_q_mma,     cudaFuncAttributeMaxDynamicSharedMemorySize, PROJ_SMEM);

    zero_cnt_kernel<<<1, 32>>>();
    build_lists_kernel<<<(NTOK_Q + 255) / 256, 256>>>(b_seq, b_seq2);
    wfrag_item_kernel<<<(NTI * 64 * 32 * 32 + 255) / 256, 256>>>(W_item);
    wfrag_q_kernel   <<<(NTQ * 32 * 32 * 32 + 255) / 256, 256>>>(W_intent);

    // Bs: gathered per-type GEMMs
    proj_item_mma<<<dim3(CAPI / MT, NTI), 256, PROJ_SMEM>>>(item, 1);
    // Ba: dense GEMM over all tokens with type 9
    proj_item_mma<<<dim3(NTOK_I / MT, 1), 256, PROJ_SMEM>>>(item, 0);
    // Q
    proj_q_mma<<<dim3(CAPQ / MT, NTQ), 256, PROJ_SMEM>>>(intent);

    attn_kernel<<<NBATCH * NH, 256, ATTN_SMEM>>>(mask, type_cnt, out);
}